// round 12
// baseline (speedup 1.0000x reference)
#include <cuda_runtime.h>
#include <cuda_fp16.h>
#include <cstdint>
typedef uint32_t u32;

#define XPP 648                       // half2 words per channel-pair plane (≡8 mod 32)
#define BW_OFF (14 * XPP)             // 9072
#define SMEM_WORDS (BW_OFF + 5184)
#define SMEM_BYTES (SMEM_WORDS * 4)   // 57024 B

__device__ __forceinline__ void mma16(float& d0, float& d1, float& d2, float& d3,
                                      u32 a0, u32 a1, u32 a2, u32 a3, u32 b0, u32 b1) {
    asm("mma.sync.aligned.m16n8k16.row.col.f32.f16.f16.f32 "
        "{%0,%1,%2,%3},{%4,%5,%6,%7},{%8,%9},{%0,%1,%2,%3};"
        : "+f"(d0), "+f"(d1), "+f"(d2), "+f"(d3)
        : "r"(a0), "r"(a1), "r"(a2), "r"(a3), "r"(b0), "r"(b1));
}

__device__ __forceinline__ u32 h2(float a, float b) {
    __half2 v = __floats2half2_rn(a, b);      // .x = a (low half)
    return *reinterpret_cast<u32*>(&v);
}

// out[b, n*32+cc, h, w] = sum_{c<16,kh,kw} x[b,(4cc-c)&127,(h-kh)&31,(w-kw)&31] * W[n,c,kh,kw]
// CTA = (g, h-quarter, b). Warp = one (h, m16 tile). M-row r -> w = 2r / 2(r-8)+1.
// One m16n8k16 fp16 mma covers a 16-channel band. 18 pipeline steps (kh x grp):
// CH planes for step s+1 and B for kh+1 are loaded during step s (explicit double
// buffering, occ-1 so the live set fits 128 regs).
__global__ __launch_bounds__(512, 1)
void fconv_mma(const float* __restrict__ x, const float* __restrict__ w,
               float* __restrict__ out)
{
    extern __shared__ u32 sm[];
    u32* xs = sm;                 // [cp<14][r<16][j<40] half2(x[2cp], x[2cp+1])
    u32* Bs = sm + BW_OFF;        // [tap][n<8][tq<4][u<2] half2(W k-pair)

    const int t = threadIdx.x;
    const int g = blockIdx.x & 7, hq = blockIdx.x >> 3, b = blockIdx.y;
    const int chb = (16 * g + 113) & 127;          // (16g - 15) mod 128
    const float* xb = x + (size_t)b * 131072;

    // ---- stage x channel-pairs, rows 8hq-8 .. 8hq+7, halo'd cols of 40 ----
    for (int i = t; i < 8960; i += 512) {
        int cp = i / 640, r2 = i % 640, r = r2 / 40, j = r2 % 40;
        int h = (8 * hq - 8 + r) & 31, wc = (j + 24) & 31;
        float f0 = xb[((chb + 2 * cp)     & 127) * 1024 + h * 32 + wc];
        float f1 = xb[((chb + 2 * cp + 1) & 127) * 1024 + h * 32 + wc];
        xs[cp * XPP + r * 40 + j] = h2(f0, f1);
    }
    // ---- stage B: Bs[((tap*8+n)*4+tq)*2+u] = half2(W[n][15-(8u+2tq)], W[n][14-8u-2tq])
    for (int i = t; i < 5184; i += 512) {
        int u = i & 1, tq = (i >> 1) & 3, n = (i >> 3) & 7, tap = i >> 6;
        int c0 = 15 - (8 * u + 2 * tq);
        Bs[i] = h2(w[n * 1296 + c0 * 81 + tap], w[n * 1296 + (c0 - 1) * 81 + tap]);
    }
    __syncthreads();

    const int lane = t & 31, wid = t >> 5, gq = lane >> 2, tq = lane & 3;
    const int hloc = wid & 7, mt = wid >> 3;
    const int h = 8 * hq + hloc;
    const u32* xbase = xs + 2 * gq + 16 * mt + tq * XPP;   // + row*40 + plane*2*XPP
    const u32* bbase = Bs + gq * 8 + tq * 2;               // + tap*64

    float acc[4][4];
    #pragma unroll
    for (int jc = 0; jc < 4; ++jc)
        #pragma unroll
        for (int q = 0; q < 4; ++q) acc[jc][q] = 0.f;

    u32  CH[2][3][10];
    uint2 BB[2][9];

    // prologue: B(kh=0) and CH(step 0 = kh0,grp0)
    #pragma unroll
    for (int kw = 0; kw < 9; ++kw)
        BB[0][kw] = *(const uint2*)(bbase + kw * 64);
    {
        const u32* xrow = xbase + (hloc + 8) * 40;
        #pragma unroll
        for (int pl = 0; pl < 3; ++pl) {
            const u32* p = xrow + (2 * (2 * pl)) * XPP;     // grp=0 planes 0,2,4
            #pragma unroll
            for (int q = 0; q < 5; ++q) {
                uint2 v = *(const uint2*)(p + 2 * q);
                CH[0][pl][2 * q] = v.x; CH[0][pl][2 * q + 1] = v.y;
            }
        }
    }

    #pragma unroll
    for (int step = 0; step < 18; ++step) {
        const int kh = step >> 1, grp = step & 1;
        const int cb = step & 1;              // CH buffer holding this step's planes

        // prefetch CH for step+1 into the other buffer
        if (step < 17) {
            const int ns = step + 1, nkh = ns >> 1, ngrp = ns & 1;
            const u32* xrow = xbase + (hloc + 8 - nkh) * 40;
            #pragma unroll
            for (int pl = 0; pl < 3; ++pl) {
                const u32* p = xrow + (2 * (ngrp + 2 * pl)) * XPP;
                #pragma unroll
                for (int q = 0; q < 5; ++q) {
                    uint2 v = *(const uint2*)(p + 2 * q);
                    CH[cb ^ 1][pl][2 * q] = v.x; CH[cb ^ 1][pl][2 * q + 1] = v.y;
                }
            }
        }
        // prefetch B for kh+1 during the grp-0 step of kh
        if (grp == 0 && kh < 8) {
            const u32* bp = bbase + (kh + 1) * 9 * 64;
            #pragma unroll
            for (int kw = 0; kw < 9; ++kw)
                BB[(kh + 1) & 1][kw] = *(const uint2*)(bp + kw * 64);
        }

        #pragma unroll
        for (int kw = 0; kw < 9; ++kw) {
            const uint2 bv = BB[kh & 1][kw];
            mma16(acc[grp][0], acc[grp][1], acc[grp][2], acc[grp][3],
                  CH[cb][0][8 - kw], CH[cb][0][9 - kw],
                  CH[cb][1][8 - kw], CH[cb][1][9 - kw], bv.x, bv.y);
            mma16(acc[grp + 2][0], acc[grp + 2][1], acc[grp + 2][2], acc[grp + 2][3],
                  CH[cb][1][8 - kw], CH[cb][1][9 - kw],
                  CH[cb][2][8 - kw], CH[cb][2][9 - kw], bv.x, bv.y);
        }
    }

    // ---- store: rows (gq, gq+8) -> w = (2gq, 2gq+1) + 16mt; cols 2tq,2tq+1 ----
    #pragma unroll
    for (int jc = 0; jc < 4; ++jc) {
        const int cc = 4 * g + jc;
        const int w0 = 2 * gq + 16 * mt;
        #pragma unroll
        for (int d = 0; d < 2; ++d) {
            const int ch = (2 * tq + d) * 32 + cc;
            float2 s = make_float2(acc[jc][d], acc[jc][2 + d]);
            *(float2*)(out + (size_t)b * 262144 + (size_t)ch * 1024
                       + h * 32 + w0) = s;
        }
    }
}

extern "C" void kernel_launch(void* const* d_in, const int* in_sizes, int n_in,
                              void* d_out, int out_size)
{
    const float* x = (const float*)d_in[0];   // (32,128,32,32) f32
    const float* w = (const float*)d_in[1];   // (8,16,9,9) f32
    float* out = (float*)d_out;               // (32,256,32,32) f32

    cudaFuncSetAttribute(fconv_mma,
                         cudaFuncAttributeMaxDynamicSharedMemorySize, SMEM_BYTES);
    dim3 grid(32, 32);                        // (g, hq) x b  -> 1024 CTAs
    fconv_mma<<<grid, 512, SMEM_BYTES>>>(x, w, out);
}

// round 13
// speedup vs baseline: 1.2519x; 1.2519x over previous
#include <cuda_runtime.h>
#include <cuda_fp16.h>
#include <cstdint>
typedef uint32_t u32;

#define XPP 968                       // plane pitch words: 24 rows * 40 + 8  (≡8 mod 32)
#define BW_OFF (14 * XPP)             // 13552
#define SMEM_WORDS (BW_OFF + 5184)
#define SMEM_BYTES (SMEM_WORDS * 4)   // 74944 B

__device__ __forceinline__ void mma16(float& d0, float& d1, float& d2, float& d3,
                                      u32 a0, u32 a1, u32 a2, u32 a3, u32 b0, u32 b1) {
    asm("mma.sync.aligned.m16n8k16.row.col.f32.f16.f16.f32 "
        "{%0,%1,%2,%3},{%4,%5,%6,%7},{%8,%9},{%0,%1,%2,%3};"
        : "+f"(d0), "+f"(d1), "+f"(d2), "+f"(d3)
        : "r"(a0), "r"(a1), "r"(a2), "r"(a3), "r"(b0), "r"(b1));
}

__device__ __forceinline__ u32 h2(float a, float b) {
    __half2 v = __floats2half2_rn(a, b);
    return *reinterpret_cast<u32*>(&v);
}

// out[b, n*32+cc, h, w] = sum_{c<16,kh,kw} x[b,(4cc-c)&127,(h-kh)&31,(w-kw)&31] * W[n,c,kh,kw]
// CTA = (g, h-half u, b): covers output rows 16u..16u+15 as two 8-row units.
// Staged x window: 24 rows r=0..23 <-> h=(16u-8+r)&31. Unit v uses r = 8v+hloc+8-kh.
// Rows 16..23 staged during unit-0 compute (at kh==3). B staged once per CTA.
__global__ __launch_bounds__(512, 2)
void fconv_mma(const float* __restrict__ x, const float* __restrict__ w,
               float* __restrict__ out)
{
    extern __shared__ u32 sm[];
    u32* xs = sm;                 // [cp<14][r<24][j<40] half2(x[2cp], x[2cp+1])
    u32* Bs = sm + BW_OFF;        // [tap][n<8][tq<4][uu<2] half2(W k-pair)

    const int t = threadIdx.x;
    const int g = blockIdx.x & 7, u = blockIdx.x >> 3, b = blockIdx.y;
    const int chb = (16 * g + 113) & 127;          // (16g - 15) mod 128
    const float* xb = x + (size_t)b * 131072;

    // ---- stage B: Bs[((tap*8+n)*4+tq)*2+uu] = half2(W[n][15-(8uu+2tq)], W[n][14-8uu-2tq])
    for (int i = t; i < 5184; i += 512) {
        int uu = i & 1, tq = (i >> 1) & 3, n = (i >> 3) & 7, tap = i >> 6;
        int c0 = 15 - (8 * uu + 2 * tq);
        Bs[i] = h2(w[n * 1296 + c0 * 81 + tap], w[n * 1296 + (c0 - 1) * 81 + tap]);
    }
    // ---- stage x rows r = 0..15 (h = 16u-8+r mod 32), mixed-radix increments ----
    {
        int j = t % 40, rp = t / 40;               // rp = pl*16 + r, < 224
        while (rp < 224) {
            int pl = rp >> 4, r = rp & 15;
            int h = (16 * u - 8 + r) & 31, wc = (j + 24) & 31;
            const float* p0 = xb + ((chb + 2 * pl) & 127) * 1024 + h * 32 + wc;
            const float* p1 = xb + ((chb + 2 * pl + 1) & 127) * 1024 + h * 32 + wc;
            xs[pl * XPP + r * 40 + j] = h2(*p0, *p1);
            j += 32; int c = j >= 40; j -= c * 40; rp += 12 + c;
        }
    }
    __syncthreads();

    const int lane = t & 31, wid = t >> 5, gq = lane >> 2, tq = lane & 3;
    const int hloc = wid & 7, mt = wid >> 3;

    #pragma unroll 1
    for (int v = 0; v < 2; ++v) {
        const int h = 16 * u + 8 * v + hloc;
        float acc[4][4];
        #pragma unroll
        for (int jc = 0; jc < 4; ++jc)
            #pragma unroll
            for (int q = 0; q < 4; ++q) acc[jc][q] = 0.f;

        #pragma unroll 1
        for (int kh = 0; kh < 9; ++kh) {
            if (v == 0 && kh == 3) {
                // ---- stage rows r = 16..23 (h = 16u+8+rr mod 32) under compute ----
                int j = t % 40, rp = t / 40;       // rp = pl*8 + rr, < 112
                while (rp < 112) {
                    int pl = rp >> 3, rr = rp & 7;
                    int hh = (16 * u + 8 + rr) & 31, wc = (j + 24) & 31;
                    const float* p0 = xb + ((chb + 2 * pl) & 127) * 1024 + hh * 32 + wc;
                    const float* p1 = xb + ((chb + 2 * pl + 1) & 127) * 1024 + hh * 32 + wc;
                    xs[pl * XPP + (16 + rr) * 40 + j] = h2(*p0, *p1);
                    j += 32; int c = j >= 40; j -= c * 40; rp += 12 + c;
                }
            }
            const int rl = 8 * v + hloc + 8 - kh;             // staged row 0..23
            const u32* xrow = xs + rl * 40 + 2 * gq + 16 * mt;
            const u32* brow = Bs + kh * 576 + gq * 8 + tq * 2;

            #pragma unroll
            for (int grp = 0; grp < 2; ++grp) {
                u32 CH[3][10];
                #pragma unroll
                for (int pl = 0; pl < 3; ++pl) {
                    const u32* p = xrow + (tq + 2 * (grp + 2 * pl)) * XPP;
                    #pragma unroll
                    for (int q = 0; q < 5; ++q) {
                        uint2 vv = *(const uint2*)(p + 2 * q);
                        CH[pl][2 * q] = vv.x; CH[pl][2 * q + 1] = vv.y;
                    }
                }
                #pragma unroll
                for (int kw = 0; kw < 9; ++kw) {
                    uint2 bv = *(const uint2*)(brow + kw * 64);
                    mma16(acc[grp][0], acc[grp][1], acc[grp][2], acc[grp][3],
                          CH[0][8 - kw], CH[0][9 - kw],
                          CH[1][8 - kw], CH[1][9 - kw], bv.x, bv.y);
                    mma16(acc[grp + 2][0], acc[grp + 2][1], acc[grp + 2][2], acc[grp + 2][3],
                          CH[1][8 - kw], CH[1][9 - kw],
                          CH[2][8 - kw], CH[2][9 - kw], bv.x, bv.y);
                }
            }
        }

        // ---- store: rows (gq, gq+8) -> w = (2gq, 2gq+1) + 16mt; cols 2tq,2tq+1 ----
        #pragma unroll
        for (int jc = 0; jc < 4; ++jc) {
            const int cc = 4 * g + jc;
            const int w0 = 2 * gq + 16 * mt;
            #pragma unroll
            for (int d = 0; d < 2; ++d) {
                const int ch = (2 * tq + d) * 32 + cc;
                float2 s = make_float2(acc[jc][d], acc[jc][2 + d]);
                *(float2*)(out + (size_t)b * 262144 + (size_t)ch * 1024
                           + h * 32 + w0) = s;
            }
        }
        if (v == 0) __syncthreads();   // rows 16..23 visible before unit 1
    }
}

extern "C" void kernel_launch(void* const* d_in, const int* in_sizes, int n_in,
                              void* d_out, int out_size)
{
    const float* x = (const float*)d_in[0];   // (32,128,32,32) f32
    const float* w = (const float*)d_in[1];   // (8,16,9,9) f32
    float* out = (float*)d_out;               // (32,256,32,32) f32

    cudaFuncSetAttribute(fconv_mma,
                         cudaFuncAttributeMaxDynamicSharedMemorySize, SMEM_BYTES);
    dim3 grid(16, 32);                        // (g, u) x b  -> 512 CTAs
    fconv_mma<<<grid, 512, SMEM_BYTES>>>(x, w, out);
}